// round 13
// baseline (speedup 1.0000x reference)
#include <cuda_runtime.h>
#include <cuda_fp16.h>
#include <cstdint>

// ---------------- problem dims ----------------
#define TOKENS 8192
#define OUTF   4096
#define INF    4096
#define GROUPS 512
#define LUTK   16
#define VEC    8

// ---------------- GEMM tiling ----------------
#define MTILE   256
#define NTILE   128
#define BK      64                  // K elems per chunk (128B per row)
#define NCHUNKS (INF / BK)          // 64
#define ASTAGE  32768               // 256 rows x 128B (swizzled block)
#define BSTAGE  16384               // 128 rows x 128B
#define STAGEB  (ASTAGE + BSTAGE)   // 49152
#define NSTAGE  4
#define SMEM_BYTES (NSTAGE * STAGEB + 64 + 1024)   // stages + mbarriers + align slack

// ---------------- device scratch (allocation-free rule: __device__ globals) ----------------
// Block-major pre-swizzled layouts:
//   g_xh: [TOKENS/256][INF/64] blocks of 32KB; within block, 16B unit at
//         (row*8 + (u ^ (row&7)))   for logical (row 0..255, u 0..7)
//   g_wh: [OUTF/128][INF/64] blocks of 16KB, same rule (row 0..127)
__device__ __align__(128) __half g_xh[TOKENS * INF];
__device__ __align__(128) __half g_wh[OUTF * INF];

// ---------------- PTX helpers (base compute_103 target: NO tcgen05/TMEM) ----------------
static __device__ __forceinline__ uint32_t smem_u32(const void* p) {
    uint32_t a;
    asm("{ .reg .u64 t; cvta.to.shared.u64 t, %1; cvt.u32.u64 %0, t; }" : "=r"(a) : "l"(p));
    return a;
}

#define MBAR_INIT(addr, cnt) \
    asm volatile("mbarrier.init.shared.b64 [%0], %1;" :: "r"((uint32_t)(addr)), "r"((uint32_t)(cnt)) : "memory")
#define MBAR_EXPECT_TX(addr, bytes) \
    asm volatile("mbarrier.arrive.expect_tx.shared.b64 _, [%0], %1;" \
                 :: "r"((uint32_t)(addr)), "r"((uint32_t)(bytes)) : "memory")
#define CP_BULK(dst, src, bytes, mbar) \
    asm volatile("cp.async.bulk.shared::cluster.global.mbarrier::complete_tx::bytes [%0], [%1], %2, [%3];" \
                 :: "r"((uint32_t)(dst)), "l"(src), "r"((uint32_t)(bytes)), "r"((uint32_t)(mbar)) : "memory")

static __device__ __forceinline__ void mbar_wait(uint32_t mbar, uint32_t parity) {
    uint32_t done;
    asm volatile(
        "{\n\t.reg .pred p;\n\t"
        "mbarrier.try_wait.parity.acquire.cta.shared::cta.b64 p, [%1], %2;\n\t"
        "selp.b32 %0, 1, 0, p;\n\t}"
        : "=r"(done) : "r"(mbar), "r"(parity) : "memory");
    if (!done) {
        asm volatile(
            "{\n\t.reg .pred P1;\n\t"
            "W_%=:\n\t"
            "mbarrier.try_wait.parity.acquire.cta.shared::cta.b64 P1, [%0], %1, 0x989680;\n\t"
            "@P1 bra.uni D_%=;\n\t"
            "bra.uni W_%=;\n\t"
            "D_%=:\n\t}"
            :: "r"(mbar), "r"(parity) : "memory");
    }
}

#define LDSM_X4(r0, r1, r2, r3, addr) \
    asm volatile("ldmatrix.sync.aligned.m8n8.x4.shared.b16 {%0,%1,%2,%3}, [%4];" \
                 : "=r"(r0), "=r"(r1), "=r"(r2), "=r"(r3) : "r"(addr))

#define MMA_F16(d, a, b) \
    asm volatile("mma.sync.aligned.m16n8k16.row.col.f32.f16.f16.f32 " \
                 "{%0,%1,%2,%3}, {%4,%5,%6,%7}, {%8,%9}, {%0,%1,%2,%3};" \
                 : "+f"((d)[0]), "+f"((d)[1]), "+f"((d)[2]), "+f"((d)[3]) \
                 : "r"((a)[0]), "r"((a)[1]), "r"((a)[2]), "r"((a)[3]), \
                   "r"((b)[0]), "r"((b)[1]))

// ---------------- Kernel 1: convert x (fp32 -> fp16, block-major swizzled) ----------------
__global__ void __launch_bounds__(256) convert_x_kernel(const float* __restrict__ x) {
    int gid = blockIdx.x * blockDim.x + threadIdx.x;   // row*512 + k8
    int row = gid >> 9;
    int k8  = gid & 511;           // 16B unit along K (8 halves)

    const float4* src = (const float4*)x + (size_t)row * (INF / 4) + k8 * 2;
    float4 v0 = src[0], v1 = src[1];
    union { uint4 u; __half2 h2[4]; } pk;
    pk.h2[0] = __floats2half2_rn(v0.x, v0.y);
    pk.h2[1] = __floats2half2_rn(v0.z, v0.w);
    pk.h2[2] = __floats2half2_rn(v1.x, v1.y);
    pk.h2[3] = __floats2half2_rn(v1.z, v1.w);

    int mb = row >> 8, r = row & 255;
    int kc = k8 >> 3,  u = k8 & 7;
    int up = u ^ (r & 7);
    size_t unit = ((size_t)(mb * (INF / BK) + kc) << 11) + r * 8 + up;   // 2048 units/block
    ((uint4*)g_xh)[unit] = pk.u;
}

// ---------------- Kernel 2: build weight (softmax-LUT mix -> fp16, block-major swizzled) ----------------
__global__ void __launch_bounds__(256) build_w_kernel(const float* __restrict__ logits,
                                                      const float* __restrict__ luts) {
    int idx = blockIdx.x * blockDim.x + threadIdx.x;   // g fastest: coalesced
    int g = idx & (GROUPS - 1);
    int o = idx >> 9;

    float acc[VEC];
#pragma unroll
    for (int v = 0; v < VEC; ++v) acc[v] = 0.f;

#pragma unroll
    for (int n = 0; n < 2; ++n) {
        const float4* lg = (const float4*)(logits + (((size_t)n * OUTF + o) * GROUPS + g) * LUTK);
        float4 t0 = lg[0], t1 = lg[1], t2 = lg[2], t3 = lg[3];
        float l[LUTK] = {t0.x, t0.y, t0.z, t0.w, t1.x, t1.y, t1.z, t1.w,
                         t2.x, t2.y, t2.z, t2.w, t3.x, t3.y, t3.z, t3.w};
        float m = l[0];
#pragma unroll
        for (int k = 1; k < LUTK; ++k) m = fmaxf(m, l[k]);
        float s = 0.f;
#pragma unroll
        for (int k = 0; k < LUTK; ++k) { l[k] = __expf(l[k] - m); s += l[k]; }
        float inv = __frcp_rn(s);
        const float4* lut4 = (const float4*)(luts + ((size_t)n * GROUPS + g) * LUTK * VEC);
#pragma unroll
        for (int k = 0; k < LUTK; ++k) {
            float wgt = l[k] * inv;
            float4 a = lut4[k * 2 + 0];
            float4 b = lut4[k * 2 + 1];
            acc[0] += wgt * a.x; acc[1] += wgt * a.y; acc[2] += wgt * a.z; acc[3] += wgt * a.w;
            acc[4] += wgt * b.x; acc[5] += wgt * b.y; acc[6] += wgt * b.z; acc[7] += wgt * b.w;
        }
    }

    union { uint4 u; __half2 h2[4]; } pk;
    pk.h2[0] = __floats2half2_rn(acc[0], acc[1]);
    pk.h2[1] = __floats2half2_rn(acc[2], acc[3]);
    pk.h2[2] = __floats2half2_rn(acc[4], acc[5]);
    pk.h2[3] = __floats2half2_rn(acc[6], acc[7]);

    int nb = o >> 7, r = o & 127;
    int kc = g >> 3, u = g & 7;
    int up = u ^ (r & 7);
    size_t unit = ((size_t)(nb * (INF / BK) + kc) << 10) + r * 8 + up;   // 1024 units/block
    ((uint4*)g_wh)[unit] = pk.u;
}

// ---------------- Kernel 3: f16 HMMA GEMM with cp.async.bulk producer ----------------
// C[8192,4096] = Xh @ Wh^T + bias (f16 in, f32 accum; rel_err ~3e-4).
// 256x128 CTA tile, 16 warps (4x4, warp tile 64x32). 4-stage ring filled by
// single-thread cp.async.bulk (2 ops/chunk) against an mbarrier — zero per-thread
// load-issue cost. ONE __syncthreads per chunk recycles the stage.
__global__ void __launch_bounds__(512, 1)
gemm_f16_kernel(const float* __restrict__ bias, float* __restrict__ out) {
    extern __shared__ char smem[];
    uint32_t sraw  = smem_u32(smem);
    uint32_t sbase = (sraw + 1023u) & ~1023u;
    const uint32_t mbarBase = sbase + NSTAGE * STAGEB;

    const int tid  = threadIdx.x;
    const int wid  = tid >> 5;
    const int lane = tid & 31;
    const int wm   = wid >> 2;       // 0..3 (64 M rows each)
    const int wn   = wid & 3;        // 0..3 (32 N cols each)

    const int mb = blockIdx.y;       // 256-row block
    const int nb = blockIdx.x;       // 128-row block
    const int m0 = mb * MTILE;
    const int n0 = nb * NTILE;

    // ---- lane constants for swizzled LDSM ----
    const int g8 = lane >> 3, r8 = lane & 7;
    // A: row = wm*64 + mt*16 + (g8&1)*8 + r8 ; k-unit = (ks*2 + (g8>>1)) ^ r8
    const uint32_t aRow0 = (uint32_t)(wm * 64 + (g8 & 1) * 8 + r8) * 128u;
    const int aKsel = g8 >> 1;
    // B: row = wn*32 + np*16 + (g8>>1)*8 + r8 ; k-unit = (ks*2 + (g8&1)) ^ r8
    const uint32_t bRow0 = (uint32_t)(wn * 32 + (g8 >> 1) * 8 + r8) * 128u;
    const int bKsel = g8 & 1;

    // ---- init mbarriers, prime pipeline ----
    if (tid == 0) {
#pragma unroll
        for (int s = 0; s < NSTAGE; ++s) MBAR_INIT(mbarBase + s * 8, 1);
    }
    __syncthreads();

    const char* aBase = (const char*)g_xh + (size_t)mb * (INF / BK) * ASTAGE;
    const char* bBase = (const char*)g_wh + (size_t)nb * (INF / BK) * BSTAGE;

    auto issue_chunk = [&](int c) {
        int s = c & (NSTAGE - 1);
        uint32_t mbar = mbarBase + s * 8;
        uint32_t dst  = sbase + (uint32_t)s * STAGEB;
        MBAR_EXPECT_TX(mbar, STAGEB);
        CP_BULK(dst,          aBase + (size_t)c * ASTAGE, ASTAGE, mbar);
        CP_BULK(dst + ASTAGE, bBase + (size_t)c * BSTAGE, BSTAGE, mbar);
    };

    if (tid == 0) {
#pragma unroll
        for (int c = 0; c < NSTAGE; ++c) issue_chunk(c);
    }

    float acc[4][4][4];
#pragma unroll
    for (int mt = 0; mt < 4; ++mt)
#pragma unroll
        for (int nt = 0; nt < 4; ++nt)
#pragma unroll
            for (int e = 0; e < 4; ++e) acc[mt][nt][e] = 0.f;

    for (int c = 0; c < NCHUNKS; ++c) {
        const int s = c & (NSTAGE - 1);
        mbar_wait(mbarBase + s * 8, (uint32_t)((c >> 2) & 1));

        const uint32_t stA = sbase + (uint32_t)s * STAGEB;
        const uint32_t stB = stA + ASTAGE;
#pragma unroll
        for (int ks = 0; ks < 4; ++ks) {
            const uint32_t aCu = (uint32_t)(((ks * 2 + aKsel) ^ r8) << 4);
            const uint32_t bCu = (uint32_t)(((ks * 2 + bKsel) ^ r8) << 4);
            uint32_t A[4][4], B[4][2];
#pragma unroll
            for (int mt = 0; mt < 4; ++mt) {
                uint32_t a = stA + aRow0 + (uint32_t)(mt * 2048) + aCu;
                LDSM_X4(A[mt][0], A[mt][1], A[mt][2], A[mt][3], a);
            }
#pragma unroll
            for (int np = 0; np < 2; ++np) {
                uint32_t b = stB + bRow0 + (uint32_t)(np * 2048) + bCu;
                uint32_t r0, r1, r2, r3;
                LDSM_X4(r0, r1, r2, r3, b);
                B[np * 2][0] = r0; B[np * 2][1] = r1;
                B[np * 2 + 1][0] = r2; B[np * 2 + 1][1] = r3;
            }
#pragma unroll
            for (int mt = 0; mt < 4; ++mt)
#pragma unroll
                for (int nt = 0; nt < 4; ++nt)
                    MMA_F16(acc[mt][nt], A[mt], B[nt]);
        }

        __syncthreads();   // all warps done reading stage s -> safe to refill
        if (tid == 0 && c + NSTAGE < NCHUNKS) issue_chunk(c + NSTAGE);
    }

    // ---- epilogue: acc + bias -> out ----
    const int cgl = (lane & 3) * 2;
    const int r0l = lane >> 2;
    const int ncol = n0 + wn * 32 + cgl;
    const float* bp = bias + ncol;
    float2 bv[4];
#pragma unroll
    for (int nt = 0; nt < 4; ++nt) bv[nt] = *(const float2*)(bp + nt * 8);

#pragma unroll
    for (int mt = 0; mt < 4; ++mt) {
        size_t row = (size_t)(m0 + wm * 64 + mt * 16 + r0l);
        float* p0 = out + row * OUTF + ncol;
        float* p1 = p0 + (size_t)8 * OUTF;
#pragma unroll
        for (int nt = 0; nt < 4; ++nt) {
            float2 v0 = {acc[mt][nt][0] + bv[nt].x, acc[mt][nt][1] + bv[nt].y};
            float2 v1 = {acc[mt][nt][2] + bv[nt].x, acc[mt][nt][3] + bv[nt].y};
            *(float2*)(p0 + nt * 8) = v0;
            *(float2*)(p1 + nt * 8) = v1;
        }
    }
}

// ---------------- launcher ----------------
extern "C" void kernel_launch(void* const* d_in, const int* in_sizes, int n_in,
                              void* d_out, int out_size) {
    const float* x      = (const float*)d_in[0];
    const float* logits = (const float*)d_in[1];
    const float* luts   = (const float*)d_in[2];
    const float* bias   = (const float*)d_in[3];
    float* out          = (float*)d_out;
    (void)in_sizes; (void)n_in; (void)out_size;

    convert_x_kernel<<<(TOKENS * (INF / 8)) / 256, 256>>>(x);
    build_w_kernel<<<(OUTF * GROUPS) / 256, 256>>>(logits, luts);

    cudaFuncSetAttribute(gemm_f16_kernel, cudaFuncAttributeMaxDynamicSharedMemorySize, SMEM_BYTES);
    dim3 grid(OUTF / NTILE, TOKENS / MTILE);   // (32, 32): n fast -> W stays L2-resident
    gemm_f16_kernel<<<grid, 512, SMEM_BYTES>>>(bias, out);
}

// round 14
// speedup vs baseline: 1.3428x; 1.3428x over previous
#include <cuda_runtime.h>
#include <cuda_fp16.h>
#include <cstdint>

// ---------------- problem dims ----------------
#define TOKENS 8192
#define OUTF   4096
#define INF    4096
#define GROUPS 512
#define LUTK   16
#define VEC    8

// ---------------- GEMM tiling ----------------
#define MTILE   256
#define NTILE   128
#define BK      64                  // K elems per chunk (128B per row)
#define NCHUNKS (INF / BK)          // 64
#define ASTAGE  32768               // A: 256 rows x 128B, pre-swizzled block (bulk-copied)
#define BROWB   144                 // B smem row: 128B data + 16 pad (conflict-free ldsm)
#define BSTAGE  (128 * BROWB)       // 18432
#define NSTAGE  3
// smem: [3 x ASTAGE][3 x BSTAGE][mbars]
#define OFF_BST (NSTAGE * ASTAGE)                  // 98304
#define OFF_MB  (OFF_BST + NSTAGE * BSTAGE)        // 153600
#define SMEM_BYTES (OFF_MB + 64 + 1024)

// ---------------- device scratch (allocation-free rule: __device__ globals) ----------------
// g_xh: block-major pre-swizzled: [TOKENS/256][INF/64] blocks of 32KB; within a block,
//       16B unit (row 0..255, u 0..7) stored at row*8 + (u ^ (row&7)).
// g_wh: plain row-major [OUTF][INF] (LDGSTS path).
__device__ __align__(128) __half g_xh[TOKENS * INF];
__device__ __align__(128) __half g_wh[OUTF * INF];

// ---------------- PTX helpers (base compute_103 target: NO tcgen05/TMEM) ----------------
static __device__ __forceinline__ uint32_t smem_u32(const void* p) {
    uint32_t a;
    asm("{ .reg .u64 t; cvta.to.shared.u64 t, %1; cvt.u32.u64 %0, t; }" : "=r"(a) : "l"(p));
    return a;
}

#define MBAR_INIT(addr, cnt) \
    asm volatile("mbarrier.init.shared.b64 [%0], %1;" :: "r"((uint32_t)(addr)), "r"((uint32_t)(cnt)) : "memory")
#define MBAR_EXPECT_TX(addr, bytes) \
    asm volatile("mbarrier.arrive.expect_tx.shared.b64 _, [%0], %1;" \
                 :: "r"((uint32_t)(addr)), "r"((uint32_t)(bytes)) : "memory")
#define CP_BULK(dst, src, bytes, mbar) \
    asm volatile("cp.async.bulk.shared::cluster.global.mbarrier::complete_tx::bytes [%0], [%1], %2, [%3];" \
                 :: "r"((uint32_t)(dst)), "l"(src), "r"((uint32_t)(bytes)), "r"((uint32_t)(mbar)) : "memory")

static __device__ __forceinline__ void mbar_wait(uint32_t mbar, uint32_t parity) {
    uint32_t done;
    asm volatile(
        "{\n\t.reg .pred p;\n\t"
        "mbarrier.try_wait.parity.acquire.cta.shared::cta.b64 p, [%1], %2;\n\t"
        "selp.b32 %0, 1, 0, p;\n\t}"
        : "=r"(done) : "r"(mbar), "r"(parity) : "memory");
    if (!done) {
        asm volatile(
            "{\n\t.reg .pred P1;\n\t"
            "W_%=:\n\t"
            "mbarrier.try_wait.parity.acquire.cta.shared::cta.b64 P1, [%0], %1, 0x989680;\n\t"
            "@P1 bra.uni D_%=;\n\t"
            "bra.uni W_%=;\n\t"
            "D_%=:\n\t}"
            :: "r"(mbar), "r"(parity) : "memory");
    }
}

#define CP16(smem_addr, gptr) \
    asm volatile("cp.async.cg.shared.global [%0], [%1], 16;" \
                 :: "r"(smem_addr), "l"(gptr) : "memory")
#define CP_COMMIT() asm volatile("cp.async.commit_group;" ::: "memory")
#define CP_WAIT1()  asm volatile("cp.async.wait_group 1;" ::: "memory")
#define CP_WAIT0()  asm volatile("cp.async.wait_group 0;" ::: "memory")

#define LDSM_X4(r0, r1, r2, r3, addr) \
    asm volatile("ldmatrix.sync.aligned.m8n8.x4.shared.b16 {%0,%1,%2,%3}, [%4];" \
                 : "=r"(r0), "=r"(r1), "=r"(r2), "=r"(r3) : "r"(addr))

#define MMA_F16(d, a, b) \
    asm volatile("mma.sync.aligned.m16n8k16.row.col.f32.f16.f16.f32 " \
                 "{%0,%1,%2,%3}, {%4,%5,%6,%7}, {%8,%9}, {%0,%1,%2,%3};" \
                 : "+f"((d)[0]), "+f"((d)[1]), "+f"((d)[2]), "+f"((d)[3]) \
                 : "r"((a)[0]), "r"((a)[1]), "r"((a)[2]), "r"((a)[3]), \
                   "r"((b)[0]), "r"((b)[1]))

// ---------------- Kernel 1: convert x (fp32 -> fp16, block-major swizzled) ----------------
__global__ void __launch_bounds__(256) convert_x_kernel(const float* __restrict__ x) {
    int gid = blockIdx.x * blockDim.x + threadIdx.x;   // row*512 + k8
    int row = gid >> 9;
    int k8  = gid & 511;           // 16B unit along K

    const float4* src = (const float4*)x + (size_t)row * (INF / 4) + k8 * 2;
    float4 v0 = src[0], v1 = src[1];
    union { uint4 u; __half2 h2[4]; } pk;
    pk.h2[0] = __floats2half2_rn(v0.x, v0.y);
    pk.h2[1] = __floats2half2_rn(v0.z, v0.w);
    pk.h2[2] = __floats2half2_rn(v1.x, v1.y);
    pk.h2[3] = __floats2half2_rn(v1.z, v1.w);

    int mb = row >> 8, r = row & 255;
    int kc = k8 >> 3,  u = k8 & 7;
    int up = u ^ (r & 7);
    size_t unit = ((size_t)(mb * (INF / BK) + kc) << 11) + r * 8 + up;   // 2048 units/block
    ((uint4*)g_xh)[unit] = pk.u;
}

// ---------------- Kernel 2: build weight (softmax-LUT mix -> fp16, row-major) ----------------
__global__ void __launch_bounds__(256) build_w_kernel(const float* __restrict__ logits,
                                                      const float* __restrict__ luts) {
    int idx = blockIdx.x * blockDim.x + threadIdx.x;   // g fastest: coalesced
    int g = idx & (GROUPS - 1);
    int o = idx >> 9;

    float acc[VEC];
#pragma unroll
    for (int v = 0; v < VEC; ++v) acc[v] = 0.f;

#pragma unroll
    for (int n = 0; n < 2; ++n) {
        const float4* lg = (const float4*)(logits + (((size_t)n * OUTF + o) * GROUPS + g) * LUTK);
        float4 t0 = lg[0], t1 = lg[1], t2 = lg[2], t3 = lg[3];
        float l[LUTK] = {t0.x, t0.y, t0.z, t0.w, t1.x, t1.y, t1.z, t1.w,
                         t2.x, t2.y, t2.z, t2.w, t3.x, t3.y, t3.z, t3.w};
        float m = l[0];
#pragma unroll
        for (int k = 1; k < LUTK; ++k) m = fmaxf(m, l[k]);
        float s = 0.f;
#pragma unroll
        for (int k = 0; k < LUTK; ++k) { l[k] = __expf(l[k] - m); s += l[k]; }
        float inv = __frcp_rn(s);
        const float4* lut4 = (const float4*)(luts + ((size_t)n * GROUPS + g) * LUTK * VEC);
#pragma unroll
        for (int k = 0; k < LUTK; ++k) {
            float wgt = l[k] * inv;
            float4 a = lut4[k * 2 + 0];
            float4 b = lut4[k * 2 + 1];
            acc[0] += wgt * a.x; acc[1] += wgt * a.y; acc[2] += wgt * a.z; acc[3] += wgt * a.w;
            acc[4] += wgt * b.x; acc[5] += wgt * b.y; acc[6] += wgt * b.z; acc[7] += wgt * b.w;
        }
    }

    union { uint4 u; __half2 h2[4]; } pk;
    pk.h2[0] = __floats2half2_rn(acc[0], acc[1]);
    pk.h2[1] = __floats2half2_rn(acc[2], acc[3]);
    pk.h2[2] = __floats2half2_rn(acc[4], acc[5]);
    pk.h2[3] = __floats2half2_rn(acc[6], acc[7]);
    ((uint4*)g_wh)[(size_t)o * (INF / 8) + g] = pk.u;
}

// ---------------- Kernel 3: f16 HMMA GEMM, hybrid producer ----------------
// A (32KB/chunk): single cp.async.bulk from pre-swizzled blocks, tid0-only mbar wait.
// B (16KB/chunk): per-thread cp.async LDGSTS (1024 ops/chunk -> LSU at half MMA time).
// 256x128 CTA tile, 16 warps (4x4, warp tile 64x32), 3-stage ring, ONE sync/chunk.
__global__ void __launch_bounds__(512, 1)
gemm_f16_kernel(const float* __restrict__ bias, float* __restrict__ out) {
    extern __shared__ char smem[];
    uint32_t sraw  = smem_u32(smem);
    uint32_t sbase = (sraw + 1023u) & ~1023u;
    const uint32_t mbarBase = sbase + OFF_MB;

    const int tid  = threadIdx.x;
    const int wid  = tid >> 5;
    const int lane = tid & 31;
    const int wm   = wid >> 2;       // 0..3 (64 M rows each)
    const int wn   = wid & 3;        // 0..3 (32 N cols each)

    const int mb = blockIdx.y;
    const int nb = blockIdx.x;
    const int m0 = mb * MTILE;
    const int n0 = nb * NTILE;

    // ---- lane constants ----
    const int g8 = lane >> 3, r8 = lane & 7;
    // A (swizzled 128B rows): row = wm*64 + mt*16 + (g8&1)*8 + r8; k-unit = (ks*2+(g8>>1))^r8
    const uint32_t aRow0 = (uint32_t)(wm * 64 + (g8 & 1) * 8 + r8) * 128u;
    const int aKsel = g8 >> 1;
    // B (padded 144B rows): bOff within 16x16 frag
    const uint32_t bOff = (uint32_t)(((g8 >> 1) * 8 + r8) * BROWB + (g8 & 1) * 16);
    const uint32_t wnRow = (uint32_t)(wn * 32 * BROWB);

    // ---- B gmem source (LDGSTS): row = tid>>2 (0..127), quarter = (tid&3)*32B, 2x16B ----
    const char* pw = (const char*)(g_wh + (size_t)(n0 + (tid >> 2)) * INF);
    const uint32_t bQuar = (uint32_t)(tid & 3) * 32u;
    const uint32_t bDst  = sbase + OFF_BST + (uint32_t)(tid >> 2) * BROWB + bQuar;

    // ---- A gmem source (bulk): contiguous 32KB blocks ----
    const char* aBase = (const char*)g_xh + (size_t)mb * (INF / BK) * ASTAGE;

    // ---- init mbarriers ----
    if (tid == 0) {
#pragma unroll
        for (int s = 0; s < NSTAGE; ++s) MBAR_INIT(mbarBase + s * 8, 1);
    }
    __syncthreads();

    auto issue_A = [&](int c) {    // tid 0 only
        int s = c % NSTAGE;
        uint32_t mbar = mbarBase + s * 8;
        MBAR_EXPECT_TX(mbar, ASTAGE);
        CP_BULK(sbase + (uint32_t)s * ASTAGE, aBase + (size_t)c * ASTAGE, ASTAGE, mbar);
    };
    auto issue_B = [&](int c) {    // all threads
        uint32_t d = bDst + (uint32_t)(c % NSTAGE) * BSTAGE;
        size_t go = (size_t)c * (BK * 2) + bQuar;
        CP16(d,      pw + go);
        CP16(d + 16, pw + go + 16);
        CP_COMMIT();
    };

    if (tid == 0) { issue_A(0); issue_A(1); }
    issue_B(0); issue_B(1);

    float acc[4][4][4];
#pragma unroll
    for (int mt = 0; mt < 4; ++mt)
#pragma unroll
        for (int nt = 0; nt < 4; ++nt)
#pragma unroll
            for (int e = 0; e < 4; ++e) acc[mt][nt][e] = 0.f;

    int aPhase = 0, wrap = 0;   // parity of stage (c % NSTAGE): flips each ring wrap
    for (int c = 0; c < NCHUNKS; ++c) {
        // B chunk c arrived (own groups), A chunk c arrived (tid0 waits, bar broadcasts)
        if (c + 2 < NCHUNKS) CP_WAIT1(); else CP_WAIT0();
        if (tid == 0) mbar_wait(mbarBase + (c % NSTAGE) * 8, (uint32_t)aPhase);
        __syncthreads();   // broadcasts A-ready; stage (c+2)%3 == (c-1)%3 now recyclable
        if (++wrap == NSTAGE) { wrap = 0; aPhase ^= 1; }

        if (c + 2 < NCHUNKS) {
            issue_B(c + 2);
            if (tid == 0) issue_A(c + 2);
        }

        const uint32_t stA = sbase + (uint32_t)(c % NSTAGE) * ASTAGE;
        const uint32_t stB = sbase + OFF_BST + (uint32_t)(c % NSTAGE) * BSTAGE;
#pragma unroll
        for (int ks = 0; ks < 4; ++ks) {
            const uint32_t aCu = (uint32_t)(((ks * 2 + aKsel) ^ r8) << 4);
            const uint32_t bK  = (uint32_t)ks * 32;
            uint32_t A[4][4], B[4][2];
#pragma unroll
            for (int mt = 0; mt < 4; ++mt) {
                uint32_t a = stA + aRow0 + (uint32_t)(mt * 2048) + aCu;
                LDSM_X4(A[mt][0], A[mt][1], A[mt][2], A[mt][3], a);
            }
#pragma unroll
            for (int np = 0; np < 2; ++np) {
                uint32_t b = stB + wnRow + (uint32_t)(np * 16 * BROWB) + bOff + bK;
                uint32_t r0, r1, r2, r3;
                LDSM_X4(r0, r1, r2, r3, b);
                B[np * 2][0] = r0; B[np * 2][1] = r1;
                B[np * 2 + 1][0] = r2; B[np * 2 + 1][1] = r3;
            }
#pragma unroll
            for (int mt = 0; mt < 4; ++mt)
#pragma unroll
                for (int nt = 0; nt < 4; ++nt)
                    MMA_F16(acc[mt][nt], A[mt], B[nt]);
        }
    }

    // ---- epilogue: acc + bias -> out ----
    const int cgl = (lane & 3) * 2;
    const int r0l = lane >> 2;
    const int ncol = n0 + wn * 32 + cgl;
    const float* bp = bias + ncol;
    float2 bv[4];
#pragma unroll
    for (int nt = 0; nt < 4; ++nt) bv[nt] = *(const float2*)(bp + nt * 8);

#pragma unroll
    for (int mt = 0; mt < 4; ++mt) {
        size_t row = (size_t)(m0 + wm * 64 + mt * 16 + r0l);
        float* p0 = out + row * OUTF + ncol;
        float* p1 = p0 + (size_t)8 * OUTF;
#pragma unroll
        for (int nt = 0; nt < 4; ++nt) {
            float2 v0 = {acc[mt][nt][0] + bv[nt].x, acc[mt][nt][1] + bv[nt].y};
            float2 v1 = {acc[mt][nt][2] + bv[nt].x, acc[mt][nt][3] + bv[nt].y};
            *(float2*)(p0 + nt * 8) = v0;
            *(float2*)(p1 + nt * 8) = v1;
        }
    }
}

// ---------------- launcher ----------------
extern "C" void kernel_launch(void* const* d_in, const int* in_sizes, int n_in,
                              void* d_out, int out_size) {
    const float* x      = (const float*)d_in[0];
    const float* logits = (const float*)d_in[1];
    const float* luts   = (const float*)d_in[2];
    const float* bias   = (const float*)d_in[3];
    float* out          = (float*)d_out;
    (void)in_sizes; (void)n_in; (void)out_size;

    convert_x_kernel<<<(TOKENS * (INF / 8)) / 256, 256>>>(x);
    build_w_kernel<<<(OUTF * GROUPS) / 256, 256>>>(logits, luts);

    cudaFuncSetAttribute(gemm_f16_kernel, cudaFuncAttributeMaxDynamicSharedMemorySize, SMEM_BYTES);
    dim3 grid(OUTF / NTILE, TOKENS / MTILE);   // (32, 32): n fast -> W stays L2-resident
    gemm_f16_kernel<<<grid, 512, SMEM_BYTES>>>(bias, out);
}

// round 15
// speedup vs baseline: 1.3461x; 1.0025x over previous
#include <cuda_runtime.h>
#include <cuda_fp16.h>
#include <cstdint>

// ---------------- problem dims ----------------
#define TOKENS 8192
#define OUTF   4096
#define INF    4096
#define GROUPS 512
#define LUTK   16
#define VEC    8

// ---------------- GEMM tiling ----------------
#define MTILE   256
#define NTILE   128
#define BK      64                  // K elems per chunk (128B per row)
#define NCHUNKS (INF / BK)          // 64
#define ASTAGE  32768               // A: 256 rows x 128B, pre-swizzled block
#define ABULK   24576               // bytes of A filled by cp.async.bulk (rows 0-191)
#define ATAIL   (ASTAGE - ABULK)    // 8192 bytes filled by LDGSTS (rows 192-255)
#define BROWB   144                 // B smem row: 128B data + 16 pad (conflict-free ldsm)
#define BSTAGE  (128 * BROWB)       // 18432
#define NSTAGE  3
// smem: [3 x ASTAGE][3 x BSTAGE][mbars]
#define OFF_BST (NSTAGE * ASTAGE)                  // 98304
#define OFF_MB  (OFF_BST + NSTAGE * BSTAGE)        // 153600
#define SMEM_BYTES (OFF_MB + 64 + 1024)

// ---------------- device scratch (allocation-free rule: __device__ globals) ----------------
// g_xh: block-major pre-swizzled: [TOKENS/256][INF/64] blocks of 32KB; within a block,
//       16B unit (row 0..255, u 0..7) stored at row*8 + (u ^ (row&7)).
// g_wh: plain row-major [OUTF][INF] (LDGSTS path).
__device__ __align__(128) __half g_xh[TOKENS * INF];
__device__ __align__(128) __half g_wh[OUTF * INF];

// ---------------- PTX helpers (base compute_103 target: NO tcgen05/TMEM) ----------------
static __device__ __forceinline__ uint32_t smem_u32(const void* p) {
    uint32_t a;
    asm("{ .reg .u64 t; cvta.to.shared.u64 t, %1; cvt.u32.u64 %0, t; }" : "=r"(a) : "l"(p));
    return a;
}

#define MBAR_INIT(addr, cnt) \
    asm volatile("mbarrier.init.shared.b64 [%0], %1;" :: "r"((uint32_t)(addr)), "r"((uint32_t)(cnt)) : "memory")
#define MBAR_EXPECT_TX(addr, bytes) \
    asm volatile("mbarrier.arrive.expect_tx.shared.b64 _, [%0], %1;" \
                 :: "r"((uint32_t)(addr)), "r"((uint32_t)(bytes)) : "memory")
#define CP_BULK(dst, src, bytes, mbar) \
    asm volatile("cp.async.bulk.shared::cluster.global.mbarrier::complete_tx::bytes [%0], [%1], %2, [%3];" \
                 :: "r"((uint32_t)(dst)), "l"(src), "r"((uint32_t)(bytes)), "r"((uint32_t)(mbar)) : "memory")

static __device__ __forceinline__ void mbar_wait(uint32_t mbar, uint32_t parity) {
    uint32_t done;
    asm volatile(
        "{\n\t.reg .pred p;\n\t"
        "mbarrier.try_wait.parity.acquire.cta.shared::cta.b64 p, [%1], %2;\n\t"
        "selp.b32 %0, 1, 0, p;\n\t}"
        : "=r"(done) : "r"(mbar), "r"(parity) : "memory");
    if (!done) {
        asm volatile(
            "{\n\t.reg .pred P1;\n\t"
            "W_%=:\n\t"
            "mbarrier.try_wait.parity.acquire.cta.shared::cta.b64 P1, [%0], %1, 0x989680;\n\t"
            "@P1 bra.uni D_%=;\n\t"
            "bra.uni W_%=;\n\t"
            "D_%=:\n\t}"
            :: "r"(mbar), "r"(parity) : "memory");
    }
}

#define CP16(smem_addr, gptr) \
    asm volatile("cp.async.cg.shared.global [%0], [%1], 16;" \
                 :: "r"(smem_addr), "l"(gptr) : "memory")
#define CP_COMMIT() asm volatile("cp.async.commit_group;" ::: "memory")
#define CP_WAIT1()  asm volatile("cp.async.wait_group 1;" ::: "memory")
#define CP_WAIT0()  asm volatile("cp.async.wait_group 0;" ::: "memory")

#define LDSM_X4(r0, r1, r2, r3, addr) \
    asm volatile("ldmatrix.sync.aligned.m8n8.x4.shared.b16 {%0,%1,%2,%3}, [%4];" \
                 : "=r"(r0), "=r"(r1), "=r"(r2), "=r"(r3) : "r"(addr))

#define MMA_F16(d, a, b) \
    asm volatile("mma.sync.aligned.m16n8k16.row.col.f32.f16.f16.f32 " \
                 "{%0,%1,%2,%3}, {%4,%5,%6,%7}, {%8,%9}, {%0,%1,%2,%3};" \
                 : "+f"((d)[0]), "+f"((d)[1]), "+f"((d)[2]), "+f"((d)[3]) \
                 : "r"((a)[0]), "r"((a)[1]), "r"((a)[2]), "r"((a)[3]), \
                   "r"((b)[0]), "r"((b)[1]))

// ---------------- Kernel 1: convert x (fp32 -> fp16, block-major swizzled) ----------------
__global__ void __launch_bounds__(256) convert_x_kernel(const float* __restrict__ x) {
    int gid = blockIdx.x * blockDim.x + threadIdx.x;   // row*512 + k8
    int row = gid >> 9;
    int k8  = gid & 511;           // 16B unit along K

    const float4* src = (const float4*)x + (size_t)row * (INF / 4) + k8 * 2;
    float4 v0 = src[0], v1 = src[1];
    union { uint4 u; __half2 h2[4]; } pk;
    pk.h2[0] = __floats2half2_rn(v0.x, v0.y);
    pk.h2[1] = __floats2half2_rn(v0.z, v0.w);
    pk.h2[2] = __floats2half2_rn(v1.x, v1.y);
    pk.h2[3] = __floats2half2_rn(v1.z, v1.w);

    int mb = row >> 8, r = row & 255;
    int kc = k8 >> 3,  u = k8 & 7;
    int up = u ^ (r & 7);
    size_t unit = ((size_t)(mb * (INF / BK) + kc) << 11) + r * 8 + up;   // 2048 units/block
    ((uint4*)g_xh)[unit] = pk.u;
}

// ---------------- Kernel 2: build weight (softmax-LUT mix -> fp16, row-major) ----------------
__global__ void __launch_bounds__(256) build_w_kernel(const float* __restrict__ logits,
                                                      const float* __restrict__ luts) {
    int idx = blockIdx.x * blockDim.x + threadIdx.x;   // g fastest: coalesced
    int g = idx & (GROUPS - 1);
    int o = idx >> 9;

    float acc[VEC];
#pragma unroll
    for (int v = 0; v < VEC; ++v) acc[v] = 0.f;

#pragma unroll
    for (int n = 0; n < 2; ++n) {
        const float4* lg = (const float4*)(logits + (((size_t)n * OUTF + o) * GROUPS + g) * LUTK);
        float4 t0 = lg[0], t1 = lg[1], t2 = lg[2], t3 = lg[3];
        float l[LUTK] = {t0.x, t0.y, t0.z, t0.w, t1.x, t1.y, t1.z, t1.w,
                         t2.x, t2.y, t2.z, t2.w, t3.x, t3.y, t3.z, t3.w};
        float m = l[0];
#pragma unroll
        for (int k = 1; k < LUTK; ++k) m = fmaxf(m, l[k]);
        float s = 0.f;
#pragma unroll
        for (int k = 0; k < LUTK; ++k) { l[k] = __expf(l[k] - m); s += l[k]; }
        float inv = __frcp_rn(s);
        const float4* lut4 = (const float4*)(luts + ((size_t)n * GROUPS + g) * LUTK * VEC);
#pragma unroll
        for (int k = 0; k < LUTK; ++k) {
            float wgt = l[k] * inv;
            float4 a = lut4[k * 2 + 0];
            float4 b = lut4[k * 2 + 1];
            acc[0] += wgt * a.x; acc[1] += wgt * a.y; acc[2] += wgt * a.z; acc[3] += wgt * a.w;
            acc[4] += wgt * b.x; acc[5] += wgt * b.y; acc[6] += wgt * b.z; acc[7] += wgt * b.w;
        }
    }

    union { uint4 u; __half2 h2[4]; } pk;
    pk.h2[0] = __floats2half2_rn(acc[0], acc[1]);
    pk.h2[1] = __floats2half2_rn(acc[2], acc[3]);
    pk.h2[2] = __floats2half2_rn(acc[4], acc[5]);
    pk.h2[3] = __floats2half2_rn(acc[6], acc[7]);
    ((uint4*)g_wh)[(size_t)o * (INF / 8) + g] = pk.u;
}

// ---------------- Kernel 3: f16 HMMA GEMM, balanced hybrid producer ----------------
// Per chunk (48KB): bulk 24KB (A rows 0-191) ~3.4k cyc; LDGSTS 24KB (A-tail 8KB linear
// + B 16KB) = 1536 ops ~3.1k cyc; MMA 4096 cyc binds.
// 256x128 CTA tile, 16 warps (4x4, warp tile 64x32), 3-stage ring, ONE sync/chunk.
__global__ void __launch_bounds__(512, 1)
gemm_f16_kernel(const float* __restrict__ bias, float* __restrict__ out) {
    extern __shared__ char smem[];
    uint32_t sraw  = smem_u32(smem);
    uint32_t sbase = (sraw + 1023u) & ~1023u;
    const uint32_t mbarBase = sbase + OFF_MB;

    const int tid  = threadIdx.x;
    const int wid  = tid >> 5;
    const int lane = tid & 31;
    const int wm   = wid >> 2;       // 0..3 (64 M rows each)
    const int wn   = wid & 3;        // 0..3 (32 N cols each)

    const int mb = blockIdx.y;
    const int nb = blockIdx.x;
    const int m0 = mb * MTILE;
    const int n0 = nb * NTILE;

    // ---- lane constants ----
    const int g8 = lane >> 3, r8 = lane & 7;
    // A (swizzled 128B rows): row = wm*64 + mt*16 + (g8&1)*8 + r8; k-unit = (ks*2+(g8>>1))^r8
    const uint32_t aRow0 = (uint32_t)(wm * 64 + (g8 & 1) * 8 + r8) * 128u;
    const int aKsel = g8 >> 1;
    // B (padded 144B rows): bOff within 16x16 frag
    const uint32_t bOff = (uint32_t)(((g8 >> 1) * 8 + r8) * BROWB + (g8 & 1) * 16);
    const uint32_t wnRow = (uint32_t)(wn * 32 * BROWB);

    // ---- B gmem source (LDGSTS): row = tid>>2 (0..127), quarter = (tid&3)*32B, 2x16B ----
    const char* pw = (const char*)(g_wh + (size_t)(n0 + (tid >> 2)) * INF);
    const uint32_t bQuar = (uint32_t)(tid & 3) * 32u;
    const uint32_t bDst  = sbase + OFF_BST + (uint32_t)(tid >> 2) * BROWB + bQuar;

    // ---- A gmem source: contiguous 32KB pre-swizzled blocks ----
    const char* aBase = (const char*)g_xh + (size_t)mb * (INF / BK) * ASTAGE;
    const uint32_t aTailOff = (uint32_t)(ABULK + tid * 16);   // linear 16B unit per thread

    // ---- init mbarriers ----
    if (tid == 0) {
#pragma unroll
        for (int s = 0; s < NSTAGE; ++s) MBAR_INIT(mbarBase + s * 8, 1);
    }
    __syncthreads();

    auto issue_A = [&](int c) {    // tid 0 only: bulk for rows 0-191
        int s = c % NSTAGE;
        uint32_t mbar = mbarBase + s * 8;
        MBAR_EXPECT_TX(mbar, ABULK);
        CP_BULK(sbase + (uint32_t)s * ASTAGE, aBase + (size_t)c * ASTAGE, ABULK, mbar);
    };
    auto issue_LDGSTS = [&](int c) {   // all threads: B (2x16B) + A-tail (1x16B)
        int s = c % NSTAGE;
        uint32_t d = bDst + (uint32_t)s * BSTAGE;
        size_t go = (size_t)c * (BK * 2) + bQuar;
        CP16(d,      pw + go);
        CP16(d + 16, pw + go + 16);
        CP16(sbase + (uint32_t)s * ASTAGE + aTailOff,
             aBase + (size_t)c * ASTAGE + aTailOff);
        CP_COMMIT();
    };

    if (tid == 0) { issue_A(0); issue_A(1); }
    issue_LDGSTS(0); issue_LDGSTS(1);

    float acc[4][4][4];
#pragma unroll
    for (int mt = 0; mt < 4; ++mt)
#pragma unroll
        for (int nt = 0; nt < 4; ++nt)
#pragma unroll
            for (int e = 0; e < 4; ++e) acc[mt][nt][e] = 0.f;

    int aPhase = 0, wrap = 0;   // parity of stage (c % NSTAGE): flips each ring wrap
    for (int c = 0; c < NCHUNKS; ++c) {
        // LDGSTS chunk c arrived (own groups); A-bulk chunk c arrived (tid0 waits, bar broadcasts)
        if (c + 2 < NCHUNKS) CP_WAIT1(); else CP_WAIT0();
        if (tid == 0) mbar_wait(mbarBase + (c % NSTAGE) * 8, (uint32_t)aPhase);
        __syncthreads();   // broadcasts A-ready; stage (c+2)%3 == (c-1)%3 now recyclable
        if (++wrap == NSTAGE) { wrap = 0; aPhase ^= 1; }

        if (c + 2 < NCHUNKS) {
            issue_LDGSTS(c + 2);
            if (tid == 0) issue_A(c + 2);
        }

        const uint32_t stA = sbase + (uint32_t)(c % NSTAGE) * ASTAGE;
        const uint32_t stB = sbase + OFF_BST + (uint32_t)(c % NSTAGE) * BSTAGE;
#pragma unroll
        for (int ks = 0; ks < 4; ++ks) {
            const uint32_t aCu = (uint32_t)(((ks * 2 + aKsel) ^ r8) << 4);
            const uint32_t bK  = (uint32_t)ks * 32;
            uint32_t A[4][4], B[4][2];
#pragma unroll
            for (int mt = 0; mt < 4; ++mt) {
                uint32_t a = stA + aRow0 + (uint32_t)(mt * 2048) + aCu;
                LDSM_X4(A[mt][0], A[mt][1], A[mt][2], A[mt][3], a);
            }
#pragma unroll
            for (int np = 0; np < 2; ++np) {
                uint32_t b = stB + wnRow + (uint32_t)(np * 16 * BROWB) + bOff + bK;
                uint32_t r0, r1, r2, r3;
                LDSM_X4(r0, r1, r2, r3, b);
                B[np * 2][0] = r0; B[np * 2][1] = r1;
                B[np * 2 + 1][0] = r2; B[np * 2 + 1][1] = r3;
            }
#pragma unroll
            for (int mt = 0; mt < 4; ++mt)
#pragma unroll
                for (int nt = 0; nt < 4; ++nt)
                    MMA_F16(acc[mt][nt], A[mt], B[nt]);
        }
    }

    // ---- epilogue: acc + bias -> out ----
    const int cgl = (lane & 3) * 2;
    const int r0l = lane >> 2;
    const int ncol = n0 + wn * 32 + cgl;
    const float* bp = bias + ncol;
    float2 bv[4];
#pragma unroll
    for (int nt = 0; nt < 4; ++nt) bv[nt] = *(const float2*)(bp + nt * 8);

#pragma unroll
    for (int mt = 0; mt < 4; ++mt) {
        size_t row = (size_t)(m0 + wm * 64 + mt * 16 + r0l);
        float* p0 = out + row * OUTF + ncol;
        float* p1 = p0 + (size_t)8 * OUTF;
#pragma unroll
        for (int nt = 0; nt < 4; ++nt) {
            float2 v0 = {acc[mt][nt][0] + bv[nt].x, acc[mt][nt][1] + bv[nt].y};
            float2 v1 = {acc[mt][nt][2] + bv[nt].x, acc[mt][nt][3] + bv[nt].y};
            *(float2*)(p0 + nt * 8) = v0;
            *(float2*)(p1 + nt * 8) = v1;
        }
    }
}

// ---------------- launcher ----------------
extern "C" void kernel_launch(void* const* d_in, const int* in_sizes, int n_in,
                              void* d_out, int out_size) {
    const float* x      = (const float*)d_in[0];
    const float* logits = (const float*)d_in[1];
    const float* luts   = (const float*)d_in[2];
    const float* bias   = (const float*)d_in[3];
    float* out          = (float*)d_out;
    (void)in_sizes; (void)n_in; (void)out_size;

    convert_x_kernel<<<(TOKENS * (INF / 8)) / 256, 256>>>(x);
    build_w_kernel<<<(OUTF * GROUPS) / 256, 256>>>(logits, luts);

    cudaFuncSetAttribute(gemm_f16_kernel, cudaFuncAttributeMaxDynamicSharedMemorySize, SMEM_BYTES);
    dim3 grid(OUTF / NTILE, TOKENS / MTILE);   // (32, 32): n fast -> W stays L2-resident
    gemm_f16_kernel<<<grid, 512, SMEM_BYTES>>>(bias, out);
}

// round 16
// speedup vs baseline: 1.3524x; 1.0047x over previous
#include <cuda_runtime.h>
#include <cuda_fp16.h>
#include <cstdint>

// ---------------- problem dims ----------------
#define TOKENS 8192
#define OUTF   4096
#define INF    4096
#define GROUPS 512
#define LUTK   16
#define VEC    8

// ---------------- GEMM tiling ----------------
#define MTILE   256
#define NTILE   128
#define BK      64                  // K elems per chunk (128B per row)
#define NCHUNKS (INF / BK)          // 64
#define ASTAGE  32768               // A: 256 rows x 128B, pre-swizzled block
#define ABULK   28672               // bytes of A via cp.async.bulk (rows 0-223)
#define ATAIL   (ASTAGE - ABULK)    // 4096 bytes via LDGSTS (rows 224-255), 256 units
#define BROWB   144                 // B smem row: 128B data + 16 pad (conflict-free ldsm)
#define BSTAGE  (128 * BROWB)       // 18432
#define NSTAGE  3
// smem: [3 x ASTAGE][3 x BSTAGE][mbars]
#define OFF_BST (NSTAGE * ASTAGE)                  // 98304
#define OFF_MB  (OFF_BST + NSTAGE * BSTAGE)        // 153600
#define SMEM_BYTES (OFF_MB + 64 + 1024)

// ---------------- device scratch (allocation-free rule: __device__ globals) ----------------
// g_xh: block-major pre-swizzled: [TOKENS/256][INF/64] blocks of 32KB; within a block,
//       16B unit (row 0..255, u 0..7) stored at row*8 + (u ^ (row&7)).
// g_wh: plain row-major [OUTF][INF] (LDGSTS path).
__device__ __align__(128) __half g_xh[TOKENS * INF];
__device__ __align__(128) __half g_wh[OUTF * INF];

// ---------------- PTX helpers (base compute_103 target: NO tcgen05/TMEM) ----------------
static __device__ __forceinline__ uint32_t smem_u32(const void* p) {
    uint32_t a;
    asm("{ .reg .u64 t; cvta.to.shared.u64 t, %1; cvt.u32.u64 %0, t; }" : "=r"(a) : "l"(p));
    return a;
}

#define MBAR_INIT(addr, cnt) \
    asm volatile("mbarrier.init.shared.b64 [%0], %1;" :: "r"((uint32_t)(addr)), "r"((uint32_t)(cnt)) : "memory")
#define MBAR_EXPECT_TX(addr, bytes) \
    asm volatile("mbarrier.arrive.expect_tx.shared.b64 _, [%0], %1;" \
                 :: "r"((uint32_t)(addr)), "r"((uint32_t)(bytes)) : "memory")
#define CP_BULK(dst, src, bytes, mbar) \
    asm volatile("cp.async.bulk.shared::cluster.global.mbarrier::complete_tx::bytes [%0], [%1], %2, [%3];" \
                 :: "r"((uint32_t)(dst)), "l"(src), "r"((uint32_t)(bytes)), "r"((uint32_t)(mbar)) : "memory")

static __device__ __forceinline__ void mbar_wait(uint32_t mbar, uint32_t parity) {
    uint32_t done;
    asm volatile(
        "{\n\t.reg .pred p;\n\t"
        "mbarrier.try_wait.parity.acquire.cta.shared::cta.b64 p, [%1], %2;\n\t"
        "selp.b32 %0, 1, 0, p;\n\t}"
        : "=r"(done) : "r"(mbar), "r"(parity) : "memory");
    if (!done) {
        asm volatile(
            "{\n\t.reg .pred P1;\n\t"
            "W_%=:\n\t"
            "mbarrier.try_wait.parity.acquire.cta.shared::cta.b64 P1, [%0], %1, 0x989680;\n\t"
            "@P1 bra.uni D_%=;\n\t"
            "bra.uni W_%=;\n\t"
            "D_%=:\n\t}"
            :: "r"(mbar), "r"(parity) : "memory");
    }
}

#define CP16(smem_addr, gptr) \
    asm volatile("cp.async.cg.shared.global [%0], [%1], 16;" \
                 :: "r"(smem_addr), "l"(gptr) : "memory")
#define CP_COMMIT() asm volatile("cp.async.commit_group;" ::: "memory")
#define CP_WAIT1()  asm volatile("cp.async.wait_group 1;" ::: "memory")
#define CP_WAIT0()  asm volatile("cp.async.wait_group 0;" ::: "memory")

#define LDSM_X4(r0, r1, r2, r3, addr) \
    asm volatile("ldmatrix.sync.aligned.m8n8.x4.shared.b16 {%0,%1,%2,%3}, [%4];" \
                 : "=r"(r0), "=r"(r1), "=r"(r2), "=r"(r3) : "r"(addr))

#define MMA_F16(d, a, b) \
    asm volatile("mma.sync.aligned.m16n8k16.row.col.f32.f16.f16.f32 " \
                 "{%0,%1,%2,%3}, {%4,%5,%6,%7}, {%8,%9}, {%0,%1,%2,%3};" \
                 : "+f"((d)[0]), "+f"((d)[1]), "+f"((d)[2]), "+f"((d)[3]) \
                 : "r"((a)[0]), "r"((a)[1]), "r"((a)[2]), "r"((a)[3]), \
                   "r"((b)[0]), "r"((b)[1]))

// ---------------- Kernel 1: convert x (fp32 -> fp16, block-major swizzled) ----------------
__global__ void __launch_bounds__(256) convert_x_kernel(const float* __restrict__ x) {
    int gid = blockIdx.x * blockDim.x + threadIdx.x;   // row*512 + k8
    int row = gid >> 9;
    int k8  = gid & 511;           // 16B unit along K

    const float4* src = (const float4*)x + (size_t)row * (INF / 4) + k8 * 2;
    float4 v0 = src[0], v1 = src[1];
    union { uint4 u; __half2 h2[4]; } pk;
    pk.h2[0] = __floats2half2_rn(v0.x, v0.y);
    pk.h2[1] = __floats2half2_rn(v0.z, v0.w);
    pk.h2[2] = __floats2half2_rn(v1.x, v1.y);
    pk.h2[3] = __floats2half2_rn(v1.z, v1.w);

    int mb = row >> 8, r = row & 255;
    int kc = k8 >> 3,  u = k8 & 7;
    int up = u ^ (r & 7);
    size_t unit = ((size_t)(mb * (INF / BK) + kc) << 11) + r * 8 + up;   // 2048 units/block
    ((uint4*)g_xh)[unit] = pk.u;
}

// ---------------- Kernel 2: build weight (softmax-LUT mix -> fp16, row-major) ----------------
__global__ void __launch_bounds__(256) build_w_kernel(const float* __restrict__ logits,
                                                      const float* __restrict__ luts) {
    int idx = blockIdx.x * blockDim.x + threadIdx.x;   // g fastest: coalesced
    int g = idx & (GROUPS - 1);
    int o = idx >> 9;

    float acc[VEC];
#pragma unroll
    for (int v = 0; v < VEC; ++v) acc[v] = 0.f;

#pragma unroll
    for (int n = 0; n < 2; ++n) {
        const float4* lg = (const float4*)(logits + (((size_t)n * OUTF + o) * GROUPS + g) * LUTK);
        float4 t0 = lg[0], t1 = lg[1], t2 = lg[2], t3 = lg[3];
        float l[LUTK] = {t0.x, t0.y, t0.z, t0.w, t1.x, t1.y, t1.z, t1.w,
                         t2.x, t2.y, t2.z, t2.w, t3.x, t3.y, t3.z, t3.w};
        float m = l[0];
#pragma unroll
        for (int k = 1; k < LUTK; ++k) m = fmaxf(m, l[k]);
        float s = 0.f;
#pragma unroll
        for (int k = 0; k < LUTK; ++k) { l[k] = __expf(l[k] - m); s += l[k]; }
        float inv = __frcp_rn(s);
        const float4* lut4 = (const float4*)(luts + ((size_t)n * GROUPS + g) * LUTK * VEC);
#pragma unroll
        for (int k = 0; k < LUTK; ++k) {
            float wgt = l[k] * inv;
            float4 a = lut4[k * 2 + 0];
            float4 b = lut4[k * 2 + 1];
            acc[0] += wgt * a.x; acc[1] += wgt * a.y; acc[2] += wgt * a.z; acc[3] += wgt * a.w;
            acc[4] += wgt * b.x; acc[5] += wgt * b.y; acc[6] += wgt * b.z; acc[7] += wgt * b.w;
        }
    }

    union { uint4 u; __half2 h2[4]; } pk;
    pk.h2[0] = __floats2half2_rn(acc[0], acc[1]);
    pk.h2[1] = __floats2half2_rn(acc[2], acc[3]);
    pk.h2[2] = __floats2half2_rn(acc[4], acc[5]);
    pk.h2[3] = __floats2half2_rn(acc[6], acc[7]);
    ((uint4*)g_wh)[(size_t)o * (INF / 8) + g] = pk.u;
}

// ---------------- Kernel 3: f16 HMMA GEMM, LSU-balanced hybrid producer ----------------
// Engine budget per chunk per SMSP: MMA 4096 cyc; bulk 28KB/7.3 ~= 3925 cyc;
// LSU = LDGSTS (1280 ops/4)*8 = 2560 + LDSM (1536/4)*4 = 1536 -> 4096 cyc. Balanced.
// 256x128 CTA tile, 16 warps (4x4, warp tile 64x32), 3-stage ring, ONE sync/chunk.
__global__ void __launch_bounds__(512, 1)
gemm_f16_kernel(const float* __restrict__ bias, float* __restrict__ out) {
    extern __shared__ char smem[];
    uint32_t sraw  = smem_u32(smem);
    uint32_t sbase = (sraw + 1023u) & ~1023u;
    const uint32_t mbarBase = sbase + OFF_MB;

    const int tid  = threadIdx.x;
    const int wid  = tid >> 5;
    const int lane = tid & 31;
    const int wm   = wid >> 2;       // 0..3 (64 M rows each)
    const int wn   = wid & 3;        // 0..3 (32 N cols each)

    const int mb = blockIdx.y;
    const int nb = blockIdx.x;
    const int m0 = mb * MTILE;
    const int n0 = nb * NTILE;

    // ---- lane constants ----
    const int g8 = lane >> 3, r8 = lane & 7;
    // A (swizzled 128B rows): row = wm*64 + mt*16 + (g8&1)*8 + r8; k-unit = (ks*2+(g8>>1))^r8
    const uint32_t aRow0 = (uint32_t)(wm * 64 + (g8 & 1) * 8 + r8) * 128u;
    const int aKsel = g8 >> 1;
    // B (padded 144B rows): bOff within 16x16 frag
    const uint32_t bOff = (uint32_t)(((g8 >> 1) * 8 + r8) * BROWB + (g8 & 1) * 16);
    const uint32_t wnRow = (uint32_t)(wn * 32 * BROWB);

    // ---- B gmem source (LDGSTS): row = tid>>2 (0..127), quarter = (tid&3)*32B, 2x16B ----
    const char* pw = (const char*)(g_wh + (size_t)(n0 + (tid >> 2)) * INF);
    const uint32_t bQuar = (uint32_t)(tid & 3) * 32u;
    const uint32_t bDst  = sbase + OFF_BST + (uint32_t)(tid >> 2) * BROWB + bQuar;

    // ---- A gmem source: contiguous 32KB pre-swizzled blocks ----
    const char* aBase = (const char*)g_xh + (size_t)mb * (INF / BK) * ASTAGE;
    const uint32_t aTailOff = (uint32_t)(ABULK + tid * 16);   // valid for tid < 256
    const bool doTail = (tid < ATAIL / 16);                   // warps 0-7 (uniform per warp)

    // ---- init mbarriers ----
    if (tid == 0) {
#pragma unroll
        for (int s = 0; s < NSTAGE; ++s) MBAR_INIT(mbarBase + s * 8, 1);
    }
    __syncthreads();

    auto issue_A = [&](int c) {    // tid 0 only: bulk for rows 0-223
        int s = c % NSTAGE;
        uint32_t mbar = mbarBase + s * 8;
        MBAR_EXPECT_TX(mbar, ABULK);
        CP_BULK(sbase + (uint32_t)s * ASTAGE, aBase + (size_t)c * ASTAGE, ABULK, mbar);
    };
    auto issue_LDGSTS = [&](int c) {   // all threads: B (2x16B); tid<256 also A-tail (1x16B)
        int s = c % NSTAGE;
        uint32_t d = bDst + (uint32_t)s * BSTAGE;
        size_t go = (size_t)c * (BK * 2) + bQuar;
        CP16(d,      pw + go);
        CP16(d + 16, pw + go + 16);
        if (doTail)
            CP16(sbase + (uint32_t)s * ASTAGE + aTailOff,
                 aBase + (size_t)c * ASTAGE + aTailOff);
        CP_COMMIT();
    };

    if (tid == 0) { issue_A(0); issue_A(1); }
    issue_LDGSTS(0); issue_LDGSTS(1);

    float acc[4][4][4];
#pragma unroll
    for (int mt = 0; mt < 4; ++mt)
#pragma unroll
        for (int nt = 0; nt < 4; ++nt)
#pragma unroll
            for (int e = 0; e < 4; ++e) acc[mt][nt][e] = 0.f;

    int aPhase = 0, wrap = 0;   // parity of stage (c % NSTAGE): flips each ring wrap
    for (int c = 0; c < NCHUNKS; ++c) {
        // LDGSTS chunk c arrived (own groups); A-bulk chunk c arrived (tid0 waits, bar broadcasts)
        if (c + 2 < NCHUNKS) CP_WAIT1(); else CP_WAIT0();
        if (tid == 0) mbar_wait(mbarBase + (c % NSTAGE) * 8, (uint32_t)aPhase);
        __syncthreads();   // broadcasts A-ready; stage (c+2)%3 == (c-1)%3 now recyclable
        if (++wrap == NSTAGE) { wrap = 0; aPhase ^= 1; }

        if (c + 2 < NCHUNKS) {
            issue_LDGSTS(c + 2);
            if (tid == 0) issue_A(c + 2);
        }

        const uint32_t stA = sbase + (uint32_t)(c % NSTAGE) * ASTAGE;
        const uint32_t stB = sbase + OFF_BST + (uint32_t)(c % NSTAGE) * BSTAGE;
#pragma unroll
        for (int ks = 0; ks < 4; ++ks) {
            const uint32_t aCu = (uint32_t)(((ks * 2 + aKsel) ^ r8) << 4);
            const uint32_t bK  = (uint32_t)ks * 32;
            uint32_t A[4][4], B[4][2];
#pragma unroll
            for (int mt = 0; mt < 4; ++mt) {
                uint32_t a = stA + aRow0 + (uint32_t)(mt * 2048) + aCu;
                LDSM_X4(A[mt][0], A[mt][1], A[mt][2], A[mt][3], a);
            }
#pragma unroll
            for (int np = 0; np < 2; ++np) {
                uint32_t b = stB + wnRow + (uint32_t)(np * 16 * BROWB) + bOff + bK;
                uint32_t r0, r1, r2, r3;
                LDSM_X4(r0, r1, r2, r3, b);
                B[np * 2][0] = r0; B[np * 2][1] = r1;
                B[np * 2 + 1][0] = r2; B[np * 2 + 1][1] = r3;
            }
#pragma unroll
            for (int mt = 0; mt < 4; ++mt)
#pragma unroll
                for (int nt = 0; nt < 4; ++nt)
                    MMA_F16(acc[mt][nt], A[mt], B[nt]);
        }
    }

    // ---- epilogue: acc + bias -> out ----
    const int cgl = (lane & 3) * 2;
    const int r0l = lane >> 2;
    const int ncol = n0 + wn * 32 + cgl;
    const float* bp = bias + ncol;
    float2 bv[4];
#pragma unroll
    for (int nt = 0; nt < 4; ++nt) bv[nt] = *(const float2*)(bp + nt * 8);

#pragma unroll
    for (int mt = 0; mt < 4; ++mt) {
        size_t row = (size_t)(m0 + wm * 64 + mt * 16 + r0l);
        float* p0 = out + row * OUTF + ncol;
        float* p1 = p0 + (size_t)8 * OUTF;
#pragma unroll
        for (int nt = 0; nt < 4; ++nt) {
            float2 v0 = {acc[mt][nt][0] + bv[nt].x, acc[mt][nt][1] + bv[nt].y};
            float2 v1 = {acc[mt][nt][2] + bv[nt].x, acc[mt][nt][3] + bv[nt].y};
            *(float2*)(p0 + nt * 8) = v0;
            *(float2*)(p1 + nt * 8) = v1;
        }
    }
}

// ---------------- launcher ----------------
extern "C" void kernel_launch(void* const* d_in, const int* in_sizes, int n_in,
                              void* d_out, int out_size) {
    const float* x      = (const float*)d_in[0];
    const float* logits = (const float*)d_in[1];
    const float* luts   = (const float*)d_in[2];
    const float* bias   = (const float*)d_in[3];
    float* out          = (float*)d_out;
    (void)in_sizes; (void)n_in; (void)out_size;

    convert_x_kernel<<<(TOKENS * (INF / 8)) / 256, 256>>>(x);
    build_w_kernel<<<(OUTF * GROUPS) / 256, 256>>>(logits, luts);

    cudaFuncSetAttribute(gemm_f16_kernel, cudaFuncAttributeMaxDynamicSharedMemorySize, SMEM_BYTES);
    dim3 grid(OUTF / NTILE, TOKENS / MTILE);   // (32, 32): n fast -> W stays L2-resident
    gemm_f16_kernel<<<grid, 512, SMEM_BYTES>>>(bias, out);
}

// round 17
// speedup vs baseline: 1.4727x; 1.0890x over previous
#include <cuda_runtime.h>
#include <cuda_fp16.h>
#include <cstdint>

// ---------------- problem dims ----------------
#define TOKENS 8192
#define OUTF   4096
#define INF    4096
#define GROUPS 512
#define LUTK   16
#define VEC    8

// ---------------- GEMM tiling ----------------
#define MTILE   256
#define NTILE   128
#define BK      64                  // K elems per chunk (128B per row)
#define NCHUNKS (INF / BK)          // 64
#define NPAIRS  (NCHUNKS / 2)       // 32: two chunks consumed per sync
#define ASTAGE  32768               // A: 256 rows x 128B, pre-swizzled block
#define ABULK   28672               // bytes of A via cp.async.bulk (rows 0-223)
#define ATAIL   (ASTAGE - ABULK)    // 4096 bytes via LDGSTS (rows 224-255), 256 units
#define BROWB   144                 // B smem row: 128B data + 16 pad (conflict-free ldsm)
#define BSTAGE  (128 * BROWB)       // 18432
#define NSTAGE  4
// smem: [4 x ASTAGE][4 x BSTAGE][mbars]
#define OFF_BST (NSTAGE * ASTAGE)                  // 131072
#define OFF_MB  (OFF_BST + NSTAGE * BSTAGE)        // 204800
#define SMEM_BYTES (OFF_MB + 64 + 1024)            // ~205.9 KB (< 227 KB opt-in)

// ---------------- device scratch (allocation-free rule: __device__ globals) ----------------
// g_xh: block-major pre-swizzled: [TOKENS/256][INF/64] blocks of 32KB; within a block,
//       16B unit (row 0..255, u 0..7) stored at row*8 + (u ^ (row&7)).
// g_wh: plain row-major [OUTF][INF] (LDGSTS path).
__device__ __align__(128) __half g_xh[TOKENS * INF];
__device__ __align__(128) __half g_wh[OUTF * INF];

// ---------------- PTX helpers (base compute_103 target: NO tcgen05/TMEM) ----------------
static __device__ __forceinline__ uint32_t smem_u32(const void* p) {
    uint32_t a;
    asm("{ .reg .u64 t; cvta.to.shared.u64 t, %1; cvt.u32.u64 %0, t; }" : "=r"(a) : "l"(p));
    return a;
}

#define MBAR_INIT(addr, cnt) \
    asm volatile("mbarrier.init.shared.b64 [%0], %1;" :: "r"((uint32_t)(addr)), "r"((uint32_t)(cnt)) : "memory")
#define MBAR_EXPECT_TX(addr, bytes) \
    asm volatile("mbarrier.arrive.expect_tx.shared.b64 _, [%0], %1;" \
                 :: "r"((uint32_t)(addr)), "r"((uint32_t)(bytes)) : "memory")
#define CP_BULK(dst, src, bytes, mbar) \
    asm volatile("cp.async.bulk.shared::cluster.global.mbarrier::complete_tx::bytes [%0], [%1], %2, [%3];" \
                 :: "r"((uint32_t)(dst)), "l"(src), "r"((uint32_t)(bytes)), "r"((uint32_t)(mbar)) : "memory")

static __device__ __forceinline__ void mbar_wait(uint32_t mbar, uint32_t parity) {
    uint32_t done;
    asm volatile(
        "{\n\t.reg .pred p;\n\t"
        "mbarrier.try_wait.parity.acquire.cta.shared::cta.b64 p, [%1], %2;\n\t"
        "selp.b32 %0, 1, 0, p;\n\t}"
        : "=r"(done) : "r"(mbar), "r"(parity) : "memory");
    if (!done) {
        asm volatile(
            "{\n\t.reg .pred P1;\n\t"
            "W_%=:\n\t"
            "mbarrier.try_wait.parity.acquire.cta.shared::cta.b64 P1, [%0], %1, 0x989680;\n\t"
            "@P1 bra.uni D_%=;\n\t"
            "bra.uni W_%=;\n\t"
            "D_%=:\n\t}"
            :: "r"(mbar), "r"(parity) : "memory");
    }
}

#define CP16(smem_addr, gptr) \
    asm volatile("cp.async.cg.shared.global [%0], [%1], 16;" \
                 :: "r"(smem_addr), "l"(gptr) : "memory")
#define CP_COMMIT() asm volatile("cp.async.commit_group;" ::: "memory")
#define CP_WAIT0()  asm volatile("cp.async.wait_group 0;" ::: "memory")

#define LDSM_X4(r0, r1, r2, r3, addr) \
    asm volatile("ldmatrix.sync.aligned.m8n8.x4.shared.b16 {%0,%1,%2,%3}, [%4];" \
                 : "=r"(r0), "=r"(r1), "=r"(r2), "=r"(r3) : "r"(addr))

#define MMA_F16(d, a, b) \
    asm volatile("mma.sync.aligned.m16n8k16.row.col.f32.f16.f16.f32 " \
                 "{%0,%1,%2,%3}, {%4,%5,%6,%7}, {%8,%9}, {%0,%1,%2,%3};" \
                 : "+f"((d)[0]), "+f"((d)[1]), "+f"((d)[2]), "+f"((d)[3]) \
                 : "r"((a)[0]), "r"((a)[1]), "r"((a)[2]), "r"((a)[3]), \
                   "r"((b)[0]), "r"((b)[1]))

// ---------------- Kernel 1: convert x (fp32 -> fp16, block-major swizzled) ----------------
__global__ void __launch_bounds__(256) convert_x_kernel(const float* __restrict__ x) {
    int gid = blockIdx.x * blockDim.x + threadIdx.x;   // row*512 + k8
    int row = gid >> 9;
    int k8  = gid & 511;           // 16B unit along K

    const float4* src = (const float4*)x + (size_t)row * (INF / 4) + k8 * 2;
    float4 v0 = src[0], v1 = src[1];
    union { uint4 u; __half2 h2[4]; } pk;
    pk.h2[0] = __floats2half2_rn(v0.x, v0.y);
    pk.h2[1] = __floats2half2_rn(v0.z, v0.w);
    pk.h2[2] = __floats2half2_rn(v1.x, v1.y);
    pk.h2[3] = __floats2half2_rn(v1.z, v1.w);

    int mb = row >> 8, r = row & 255;
    int kc = k8 >> 3,  u = k8 & 7;
    int up = u ^ (r & 7);
    size_t unit = ((size_t)(mb * (INF / BK) + kc) << 11) + r * 8 + up;   // 2048 units/block
    ((uint4*)g_xh)[unit] = pk.u;
}

// ---------------- Kernel 2: build weight (softmax-LUT mix -> fp16, row-major) ----------------
__global__ void __launch_bounds__(256) build_w_kernel(const float* __restrict__ logits,
                                                      const float* __restrict__ luts) {
    int idx = blockIdx.x * blockDim.x + threadIdx.x;   // g fastest: coalesced
    int g = idx & (GROUPS - 1);
    int o = idx >> 9;

    float acc[VEC];
#pragma unroll
    for (int v = 0; v < VEC; ++v) acc[v] = 0.f;

#pragma unroll
    for (int n = 0; n < 2; ++n) {
        const float4* lg = (const float4*)(logits + (((size_t)n * OUTF + o) * GROUPS + g) * LUTK);
        float4 t0 = lg[0], t1 = lg[1], t2 = lg[2], t3 = lg[3];
        float l[LUTK] = {t0.x, t0.y, t0.z, t0.w, t1.x, t1.y, t1.z, t1.w,
                         t2.x, t2.y, t2.z, t2.w, t3.x, t3.y, t3.z, t3.w};
        float m = l[0];
#pragma unroll
        for (int k = 1; k < LUTK; ++k) m = fmaxf(m, l[k]);
        float s = 0.f;
#pragma unroll
        for (int k = 0; k < LUTK; ++k) { l[k] = __expf(l[k] - m); s += l[k]; }
        float inv = __frcp_rn(s);
        const float4* lut4 = (const float4*)(luts + ((size_t)n * GROUPS + g) * LUTK * VEC);
#pragma unroll
        for (int k = 0; k < LUTK; ++k) {
            float wgt = l[k] * inv;
            float4 a = lut4[k * 2 + 0];
            float4 b = lut4[k * 2 + 1];
            acc[0] += wgt * a.x; acc[1] += wgt * a.y; acc[2] += wgt * a.z; acc[3] += wgt * a.w;
            acc[4] += wgt * b.x; acc[5] += wgt * b.y; acc[6] += wgt * b.z; acc[7] += wgt * b.w;
        }
    }

    union { uint4 u; __half2 h2[4]; } pk;
    pk.h2[0] = __floats2half2_rn(acc[0], acc[1]);
    pk.h2[1] = __floats2half2_rn(acc[2], acc[3]);
    pk.h2[2] = __floats2half2_rn(acc[4], acc[5]);
    pk.h2[3] = __floats2half2_rn(acc[6], acc[7]);
    ((uint4*)g_wh)[(size_t)o * (INF / 8) + g] = pk.u;
}

// ---------------- Kernel 3: f16 HMMA GEMM, 4-stage ring, 2 chunks per sync ----------------
// Boundary cost paid 32x instead of 64x. Engines per chunk unchanged (MMA 4096,
// bulk ~3925, LSU 4096). Refill pair cc+1 after this sync targets the stages pair
// cc-1 vacated (consumption confirmed by the sync) -> race-free.
__global__ void __launch_bounds__(512, 1)
gemm_f16_kernel(const float* __restrict__ bias, float* __restrict__ out) {
    extern __shared__ char smem[];
    uint32_t sraw  = smem_u32(smem);
    uint32_t sbase = (sraw + 1023u) & ~1023u;
    const uint32_t mbarBase = sbase + OFF_MB;

    const int tid  = threadIdx.x;
    const int wid  = tid >> 5;
    const int lane = tid & 31;
    const int wm   = wid >> 2;       // 0..3 (64 M rows each)
    const int wn   = wid & 3;        // 0..3 (32 N cols each)

    const int mb = blockIdx.y;
    const int nb = blockIdx.x;
    const int m0 = mb * MTILE;
    const int n0 = nb * NTILE;

    // ---- lane constants ----
    const int g8 = lane >> 3, r8 = lane & 7;
    const uint32_t aRow0 = (uint32_t)(wm * 64 + (g8 & 1) * 8 + r8) * 128u;
    const int aKsel = g8 >> 1;
    const uint32_t bOff = (uint32_t)(((g8 >> 1) * 8 + r8) * BROWB + (g8 & 1) * 16);
    const uint32_t wnRow = (uint32_t)(wn * 32 * BROWB);

    // ---- B gmem source (LDGSTS): row = tid>>2 (0..127), quarter = (tid&3)*32B ----
    const char* pw = (const char*)(g_wh + (size_t)(n0 + (tid >> 2)) * INF);
    const uint32_t bQuar = (uint32_t)(tid & 3) * 32u;
    const uint32_t bDst  = sbase + OFF_BST + (uint32_t)(tid >> 2) * BROWB + bQuar;

    // ---- A gmem source: contiguous 32KB pre-swizzled blocks ----
    const char* aBase = (const char*)g_xh + (size_t)mb * (INF / BK) * ASTAGE;
    const uint32_t aTailOff = (uint32_t)(ABULK + tid * 16);
    const bool doTail = (tid < ATAIL / 16);   // warps 0-7 (uniform per warp)

    // ---- init mbarriers (2, ping-pong per pair) ----
    if (tid == 0) {
        MBAR_INIT(mbarBase + 0, 1);
        MBAR_INIT(mbarBase + 8, 1);
    }
    __syncthreads();

    auto issue_bulk_pair = [&](int cp) {   // tid 0 only: A rows 0-223 of both chunks
        int c0 = cp * 2;
        uint32_t mbar = mbarBase + (uint32_t)(cp & 1) * 8;
        MBAR_EXPECT_TX(mbar, 2 * ABULK);
        CP_BULK(sbase + (uint32_t)(c0 & 3) * ASTAGE,
                aBase + (size_t)c0 * ASTAGE, ABULK, mbar);
        CP_BULK(sbase + (uint32_t)((c0 + 1) & 3) * ASTAGE,
                aBase + (size_t)(c0 + 1) * ASTAGE, ABULK, mbar);
    };
    auto issue_ldgsts_pair = [&](int cp) { // all threads: B + A-tail for both chunks, 1 group
        int c0 = cp * 2;
#pragma unroll
        for (int k = 0; k < 2; ++k) {
            int c = c0 + k;
            uint32_t d = bDst + (uint32_t)(c & 3) * BSTAGE;
            size_t go = (size_t)c * (BK * 2) + bQuar;
            CP16(d,      pw + go);
            CP16(d + 16, pw + go + 16);
            if (doTail)
                CP16(sbase + (uint32_t)(c & 3) * ASTAGE + aTailOff,
                     aBase + (size_t)c * ASTAGE + aTailOff);
        }
        CP_COMMIT();
    };

    // prologue: pair 0 in flight
    if (tid == 0) issue_bulk_pair(0);
    issue_ldgsts_pair(0);

    float acc[4][4][4];
#pragma unroll
    for (int mt = 0; mt < 4; ++mt)
#pragma unroll
        for (int nt = 0; nt < 4; ++nt)
#pragma unroll
            for (int e = 0; e < 4; ++e) acc[mt][nt][e] = 0.f;

    for (int cp = 0; cp < NPAIRS; ++cp) {
        // pair cp is the only group in flight
        CP_WAIT0();
        if (tid == 0) mbar_wait(mbarBase + (uint32_t)(cp & 1) * 8, (uint32_t)((cp >> 1) & 1));
        __syncthreads();   // broadcasts readiness; confirms pair cp-1 stages are free

        if (cp + 1 < NPAIRS) {
            issue_ldgsts_pair(cp + 1);
            if (tid == 0) issue_bulk_pair(cp + 1);
        }

#pragma unroll
        for (int kc = 0; kc < 2; ++kc) {
            const int c = cp * 2 + kc;
            const uint32_t stA = sbase + (uint32_t)(c & 3) * ASTAGE;
            const uint32_t stB = sbase + OFF_BST + (uint32_t)(c & 3) * BSTAGE;
#pragma unroll
            for (int ks = 0; ks < 4; ++ks) {
                const uint32_t aCu = (uint32_t)(((ks * 2 + aKsel) ^ r8) << 4);
                const uint32_t bK  = (uint32_t)ks * 32;
                uint32_t A[4][4], B[4][2];
#pragma unroll
                for (int mt = 0; mt < 4; ++mt) {
                    uint32_t a = stA + aRow0 + (uint32_t)(mt * 2048) + aCu;
                    LDSM_X4(A[mt][0], A[mt][1], A[mt][2], A[mt][3], a);
                }
#pragma unroll
                for (int np = 0; np < 2; ++np) {
                    uint32_t b = stB + wnRow + (uint32_t)(np * 16 * BROWB) + bOff + bK;
                    uint32_t r0, r1, r2, r3;
                    LDSM_X4(r0, r1, r2, r3, b);
                    B[np * 2][0] = r0; B[np * 2][1] = r1;
                    B[np * 2 + 1][0] = r2; B[np * 2 + 1][1] = r3;
                }
#pragma unroll
                for (int mt = 0; mt < 4; ++mt)
#pragma unroll
                    for (int nt = 0; nt < 4; ++nt)
                        MMA_F16(acc[mt][nt], A[mt], B[nt]);
            }
        }
    }

    // ---- epilogue: acc + bias -> out ----
    const int cgl = (lane & 3) * 2;
    const int r0l = lane >> 2;
    const int ncol = n0 + wn * 32 + cgl;
    const float* bp = bias + ncol;
    float2 bv[4];
#pragma unroll
    for (int nt = 0; nt < 4; ++nt) bv[nt] = *(const float2*)(bp + nt * 8);

#pragma unroll
    for (int mt = 0; mt < 4; ++mt) {
        size_t row = (size_t)(m0 + wm * 64 + mt * 16 + r0l);
        float* p0 = out + row * OUTF + ncol;
        float* p1 = p0 + (size_t)8 * OUTF;
#pragma unroll
        for (int nt = 0; nt < 4; ++nt) {
            float2 v0 = {acc[mt][nt][0] + bv[nt].x, acc[mt][nt][1] + bv[nt].y};
            float2 v1 = {acc[mt][nt][2] + bv[nt].x, acc[mt][nt][3] + bv[nt].y};
            *(float2*)(p0 + nt * 8) = v0;
            *(float2*)(p1 + nt * 8) = v1;
        }
    }
}

// ---------------- launcher ----------------
extern "C" void kernel_launch(void* const* d_in, const int* in_sizes, int n_in,
                              void* d_out, int out_size) {
    const float* x      = (const float*)d_in[0];
    const float* logits = (const float*)d_in[1];
    const float* luts   = (const float*)d_in[2];
    const float* bias   = (const float*)d_in[3];
    float* out          = (float*)d_out;
    (void)in_sizes; (void)n_in; (void)out_size;

    convert_x_kernel<<<(TOKENS * (INF / 8)) / 256, 256>>>(x);
    build_w_kernel<<<(OUTF * GROUPS) / 256, 256>>>(logits, luts);

    cudaFuncSetAttribute(gemm_f16_kernel, cudaFuncAttributeMaxDynamicSharedMemorySize, SMEM_BYTES);
    dim3 grid(OUTF / NTILE, TOKENS / MTILE);   // (32, 32): n fast -> W stays L2-resident
    gemm_f16_kernel<<<grid, 512, SMEM_BYTES>>>(bias, out);
}